// round 15
// baseline (speedup 1.0000x reference)
#include <cuda_runtime.h>
#include <cuda_fp16.h>
#include <cuda_bf16.h>
#include <cstdint>

// GNN_26242250178821: 2-layer GCN forward, CSR-gather + fp16 feature rows.
// R15: 8-edge/thread count+build (MLP 8), zeroing folded into scan
// (g_deg re-zeroed after read; invariant across graph replays), 1-block probe.
//
// RULE: never pass a __device__ symbol as a kernel argument from host code —
// on GB300/ATS the host-shadow address is silently writable.

#define D 64
#define MAXN 150016
#define MAXE  3000064
#define MAXELEM (150016 * 64)
#define MAXB 1024

__device__ int    g_deg[MAXN];     // zero at load; scan re-zeroes after use
__device__ int    g_off[MAXN + 1];
__device__ int    g_pos[MAXN];
__device__ float  g_dinv[MAXN];
__device__ int    g_bsum[MAXB];
__device__ int    g_cnt;           // zero at load; build resets after scan
__device__ int    g_src[MAXE];     // CSR payload: src index only
__device__ __half g_xwh[MAXELEM];  // rows = xw * dinv[row], fp16, 128 B/row
__device__ int    g_idx64;

// 1-block probe: dtype detect + zero sentinel row n of g_xwh.
__global__ void k_probe(const unsigned long long* __restrict__ p, int n) {
    __shared__ int any;
    if (threadIdx.x == 0) any = 0;
    __syncthreads();
    if ((p[threadIdx.x] >> 32) != 0ull) any = 1;
    if (threadIdx.x < 32)
        ((uint32_t*)g_xwh)[(size_t)n * 32 + threadIdx.x] = 0u;
    __syncthreads();
    if (threadIdx.x == 0) g_idx64 = any ? 0 : 1;
}

// Degree count: 8 edges/thread, vectorized col loads, fire-and-forget REDs.
__global__ void k_count(const void* __restrict__ ei, int e, int n) {
    long long i = ((long long)blockIdx.x * blockDim.x + threadIdx.x) * 8;
    if (i >= e) return;
    int c[8];
    int m = (e - i >= 8) ? 8 : (int)(e - i);
    size_t base = (size_t)e + i;
    if (m == 8 && (e & 3) == 0) {
        if (g_idx64) {
            #pragma unroll
            for (int q = 0; q < 4; q++) {
                longlong2 v = *(const longlong2*)((const long long*)ei + base + q * 2);
                c[q * 2] = (int)v.x; c[q * 2 + 1] = (int)v.y;
            }
        } else {
            int4 a = *(const int4*)((const int*)ei + base);
            int4 b = *(const int4*)((const int*)ei + base + 4);
            c[0]=a.x; c[1]=a.y; c[2]=a.z; c[3]=a.w;
            c[4]=b.x; c[5]=b.y; c[6]=b.z; c[7]=b.w;
        }
    } else {
        for (int t = 0; t < m; t++)
            c[t] = g_idx64 ? (int)((const long long*)ei)[base + t]
                           : ((const int*)ei)[base + t];
        for (int t = m; t < 8; t++) c[t] = -1;
    }
    #pragma unroll
    for (int t = 0; t < 8; t++)
        if ((unsigned)c[t] < (unsigned)n) atomicAdd(&g_deg[c[t]], 1);
}

// Single-kernel scan, grid-resident spin sync; re-zeroes g_deg after read.
__global__ void __launch_bounds__(256, 8) k_scan(int n) {
    __shared__ int wsum[8];
    __shared__ int s_bpre;
    int tid = threadIdx.x, lane = tid & 31, wid = tid >> 5;
    int i = blockIdx.x * 256 + tid;
    int d = (i < n) ? g_deg[i] : 0;
    if (i < n) g_deg[i] = 0;              // restore invariant for next call
    int v = d;
    #pragma unroll
    for (int o = 1; o < 32; o <<= 1) {
        int t = __shfl_up_sync(~0u, v, o);
        if (lane >= o) v += t;
    }
    if (lane == 31) wsum[wid] = v;
    __syncthreads();
    if (wid == 0 && lane < 8) {
        int w = wsum[lane];
        #pragma unroll
        for (int o = 1; o < 8; o <<= 1) {
            int t = __shfl_up_sync(0xFFu, w, o);
            if (lane >= o) w += t;
        }
        wsum[lane] = w;
    }
    __syncthreads();
    int excl_blk = v - d + (wid > 0 ? wsum[wid - 1] : 0);
    int blk_total = wsum[7];

    if (tid == 0) {
        ((volatile int*)g_bsum)[blockIdx.x] = blk_total;
        __threadfence();
        atomicAdd(&g_cnt, 1);
    }
    volatile int* cnt = &g_cnt;
    while (*cnt < (int)gridDim.x) { }
    __syncthreads();

    {
        int part = 0;
        for (int bkt = tid; bkt < (int)blockIdx.x; bkt += 256)
            part += ((volatile int*)g_bsum)[bkt];
        #pragma unroll
        for (int o = 16; o > 0; o >>= 1) part += __shfl_down_sync(~0u, part, o);
        if (lane == 0) wsum[wid] = part;
        __syncthreads();
        if (tid == 0) {
            int s = 0;
            #pragma unroll
            for (int w = 0; w < 8; w++) s += wsum[w];
            s_bpre = s;
        }
        __syncthreads();
    }

    int excl = excl_blk + s_bpre;
    if (i < n) {
        g_off[i] = excl;
        g_pos[i] = excl;
        g_dinv[i] = rsqrtf((float)d + 1.0f);
        if (i == n - 1) g_off[n] = excl + d;
    }
}

// ---------------- tensor-core GEMM core (rows scaled by dinv) --------------

__device__ __forceinline__ void ldsm_x4(uint32_t& r0, uint32_t& r1,
                                        uint32_t& r2, uint32_t& r3, uint32_t a) {
    asm volatile("ldmatrix.sync.aligned.m8n8.x4.shared.b16 {%0,%1,%2,%3},[%4];"
                 : "=r"(r0), "=r"(r1), "=r"(r2), "=r"(r3) : "r"(a));
}
__device__ __forceinline__ void ldsm_x4t(uint32_t& r0, uint32_t& r1,
                                         uint32_t& r2, uint32_t& r3, uint32_t a) {
    asm volatile("ldmatrix.sync.aligned.m8n8.x4.trans.shared.b16 {%0,%1,%2,%3},[%4];"
                 : "=r"(r0), "=r"(r1), "=r"(r2), "=r"(r3) : "r"(a));
}
__device__ __forceinline__ void mma16816(float* d, uint32_t a0, uint32_t a1,
                                         uint32_t a2, uint32_t a3,
                                         uint32_t b0, uint32_t b1) {
    asm volatile(
        "mma.sync.aligned.m16n8k16.row.col.f32.f16.f16.f32 "
        "{%0,%1,%2,%3},{%4,%5,%6,%7},{%8,%9},{%0,%1,%2,%3};"
        : "+f"(d[0]), "+f"(d[1]), "+f"(d[2]), "+f"(d[3])
        : "r"(a0), "r"(a1), "r"(a2), "r"(a3), "r"(b0), "r"(b1));
}

__device__ __forceinline__ void gemm_core(const __half* xs, const __half* Ws,
                                          int row0, int n) {
    int tid = threadIdx.x;
    int warp = tid >> 5, lane = tid & 31;
    int warpRow = warp * 16;

    float d[8][4];
    #pragma unroll
    for (int t = 0; t < 8; t++)
        #pragma unroll
        for (int q = 0; q < 4; q++) d[t][q] = 0.0f;

    int rin = lane & 15, half_sel = lane >> 4;
    #pragma unroll
    for (int ks = 0; ks < 4; ks++) {
        uint32_t a0, a1, a2, a3;
        uint32_t aaddr = (uint32_t)__cvta_generic_to_shared(
            &xs[(warpRow + rin) * 72 + ks * 16 + half_sel * 8]);
        ldsm_x4(a0, a1, a2, a3, aaddr);
        #pragma unroll
        for (int jp = 0; jp < 4; jp++) {
            uint32_t b0, b1, b2, b3;
            uint32_t baddr = (uint32_t)__cvta_generic_to_shared(
                &Ws[(ks * 16 + rin) * 72 + (jp * 2 + half_sel) * 8]);
            ldsm_x4t(b0, b1, b2, b3, baddr);
            mma16816(d[jp * 2],     a0, a1, a2, a3, b0, b1);
            mma16816(d[jp * 2 + 1], a0, a1, a2, a3, b2, b3);
        }
    }

    int group = lane >> 2, tig = lane & 3;
    int row_lo = row0 + warpRow + group;
    int row_hi = row_lo + 8;
    float dv_lo = (row_lo < n) ? g_dinv[row_lo] : 0.0f;
    float dv_hi = (row_hi < n) ? g_dinv[row_hi] : 0.0f;
    __half2* xwh2 = (__half2*)g_xwh;
    #pragma unroll
    for (int t = 0; t < 8; t++) {
        int cidx = t * 4 + tig;
        if (row_lo < n)
            xwh2[(size_t)row_lo * 32 + cidx] =
                __floats2half2_rn(d[t][0] * dv_lo, d[t][1] * dv_lo);
        if (row_hi < n)
            xwh2[(size_t)row_hi * 32 + cidx] =
                __floats2half2_rn(d[t][2] * dv_hi, d[t][3] * dv_hi);
    }
}

__device__ __forceinline__ void stage_W(const float* __restrict__ W, __half* Ws) {
    const float2* W2 = (const float2*)W;
    for (int i = threadIdx.x; i < 2048; i += 256) {
        int k = i >> 5, np = i & 31;
        float2 w = W2[i];
        *(__half2*)&Ws[k * 72 + np * 2] = __floats2half2_rn(w.x, w.y);
    }
}

// Layer-1 GEMM (fused concat-out0, dinv-scaled) grid-fused with CSR build.
// blocks [0, gemmBlocks): GEMM; blocks >= gemmBlocks: build (8 edges/thread).
__global__ void __launch_bounds__(256) k_gemm1_build(
        const float4* __restrict__ u, const float4* __restrict__ it,
        const float* __restrict__ W, float4* __restrict__ out0,
        int nu4, int n, int gemmBlocks, const void* __restrict__ ei, int e) {
    __shared__ __half xs[128 * 72];
    __shared__ __half Ws[64 * 72];

    if (blockIdx.x >= (unsigned)gemmBlocks) {
        if (blockIdx.x == (unsigned)gemmBlocks && threadIdx.x == 0)
            g_cnt = 0;   // reset scan spin counter for next call
        int bid = blockIdx.x - gemmBlocks;
        long long i = ((long long)bid * 256 + threadIdx.x) * 8;
        if (i >= e) return;
        int r[8], c[8];
        int m = (e - i >= 8) ? 8 : (int)(e - i);
        size_t cb = (size_t)e + i;
        if (m == 8 && (e & 3) == 0) {
            if (g_idx64) {
                #pragma unroll
                for (int q = 0; q < 4; q++) {
                    longlong2 rv = *(const longlong2*)((const long long*)ei + i + q * 2);
                    longlong2 cv = *(const longlong2*)((const long long*)ei + cb + q * 2);
                    r[q * 2] = (int)rv.x; r[q * 2 + 1] = (int)rv.y;
                    c[q * 2] = (int)cv.x; c[q * 2 + 1] = (int)cv.y;
                }
            } else {
                int4 ra = *(const int4*)((const int*)ei + i);
                int4 rb = *(const int4*)((const int*)ei + i + 4);
                int4 ca = *(const int4*)((const int*)ei + cb);
                int4 cc = *(const int4*)((const int*)ei + cb + 4);
                r[0]=ra.x; r[1]=ra.y; r[2]=ra.z; r[3]=ra.w;
                r[4]=rb.x; r[5]=rb.y; r[6]=rb.z; r[7]=rb.w;
                c[0]=ca.x; c[1]=ca.y; c[2]=ca.z; c[3]=ca.w;
                c[4]=cc.x; c[5]=cc.y; c[6]=cc.z; c[7]=cc.w;
            }
        } else {
            for (int t = 0; t < m; t++) {
                if (g_idx64) {
                    r[t] = (int)((const long long*)ei)[i + t];
                    c[t] = (int)((const long long*)ei)[cb + t];
                } else {
                    r[t] = ((const int*)ei)[i + t];
                    c[t] = ((const int*)ei)[cb + t];
                }
            }
            for (int t = m; t < 8; t++) { r[t] = -1; c[t] = -1; }
        }
        #pragma unroll
        for (int t = 0; t < 8; t++) {
            if ((unsigned)r[t] < (unsigned)n && (unsigned)c[t] < (unsigned)n) {
                int p = atomicAdd(&g_pos[c[t]], 1);
                g_src[p] = r[t];
            }
        }
        return;
    }

    int tid = threadIdx.x;
    int row0 = blockIdx.x * 128;
    int nr = n - row0; if (nr > 128) nr = 128;

    stage_W(W, Ws);
    {
        int tot4 = nr * 16, g0 = row0 * 16;
        for (int i = tid; i < tot4; i += 256) {
            int gi = g0 + i;
            float4 v = (gi < nu4) ? u[gi] : it[gi - nu4];
            out0[gi] = v;
            int row = i >> 4, k4 = i & 15;
            __half2* p = (__half2*)&xs[row * 72 + k4 * 4];
            p[0] = __floats2half2_rn(v.x, v.y);
            p[1] = __floats2half2_rn(v.z, v.w);
        }
        for (int i = nr * 16 + tid; i < 128 * 16; i += 256) {
            int row = i >> 4, k4 = i & 15;
            __half2* p = (__half2*)&xs[row * 72 + k4 * 4];
            p[0] = __half2half2(__float2half(0.0f));
            p[1] = __half2half2(__float2half(0.0f));
        }
    }
    __syncthreads();
    gemm_core(xs, Ws, row0, n);
}

// Layer-2 GEMM: reads out1 fp32 with relu, stores dinv-scaled rows.
__global__ void __launch_bounds__(256) k_gemm_l2(
        const float* __restrict__ x, const float* __restrict__ W, int n) {
    __shared__ __half xs[128 * 72];
    __shared__ __half Ws[64 * 72];
    int tid = threadIdx.x;
    int row0 = blockIdx.x * 128;
    int nr = n - row0; if (nr > 128) nr = 128;

    stage_W(W, Ws);
    {
        const float4* x4 = (const float4*)(x + (size_t)row0 * 64);
        int tot4 = nr * 16;
        for (int i = tid; i < tot4; i += 256) {
            float4 v = x4[i];
            v.x = fmaxf(v.x, 0.0f); v.y = fmaxf(v.y, 0.0f);
            v.z = fmaxf(v.z, 0.0f); v.w = fmaxf(v.w, 0.0f);
            int row = i >> 4, k4 = i & 15;
            __half2* p = (__half2*)&xs[row * 72 + k4 * 4];
            p[0] = __floats2half2_rn(v.x, v.y);
            p[1] = __floats2half2_rn(v.z, v.w);
        }
        for (int i = nr * 16 + tid; i < 128 * 16; i += 256) {
            int row = i >> 4, k4 = i & 15;
            __half2* p = (__half2*)&xs[row * 72 + k4 * 4];
            p[0] = __half2half2(__float2half(0.0f));
            p[1] = __half2half2(__float2half(0.0f));
        }
    }
    __syncthreads();
    gemm_core(xs, Ws, row0, n);
}

// Warp per node; lane owns dims {2*lane, 2*lane+1}. Rows pre-scaled by
// dinv[src]; OOB lanes use sentinel zero row n.
// out[i] = dinv[i] * (sum + xws[i]) + b
__global__ void k_agg(const float* __restrict__ b, float* __restrict__ out, int n) {
    int node = (blockIdx.x * blockDim.x + threadIdx.x) >> 5;
    int lane = threadIdx.x & 31;
    if (node >= n) return;

    int p0 = g_off[node];
    int p1 = g_off[node + 1];
    float acc0 = 0.0f, acc1 = 0.0f;

    const __half2* xw2 = (const __half2*)g_xwh;

    int p = p0;
    while (p < p1) {
        int cnt = p1 - p; if (cnt > 32) cnt = 32;
        int meta = n;                       // sentinel zero row
        if (p + lane < p1) meta = __ldg(&g_src[p + lane]);

        int nb = (cnt + 7) >> 3;
        for (int jb = 0; jb < nb; jb++) {
            __half2 h[8];
            #pragma unroll
            for (int t = 0; t < 8; t++) {
                unsigned r = (unsigned)__shfl_sync(~0u, meta, jb * 8 + t);
                h[t] = __ldg(&xw2[r * 32u + (unsigned)lane]);
            }
            #pragma unroll
            for (int t = 0; t < 8; t++) {
                float2 f = __half22float2(h[t]);
                acc0 += f.x;
                acc1 += f.y;
            }
        }
        p += cnt;
    }

    float di = g_dinv[node];
    float2 fs = __half22float2(xw2[(unsigned)node * 32u + (unsigned)lane]);
    float2 bb = ((const float2*)b)[lane];
    float2 o;
    o.x = fmaf(di, acc0 + fs.x, bb.x);
    o.y = fmaf(di, acc1 + fs.y, bb.y);
    ((float2*)out)[(unsigned)node * 32u + (unsigned)lane] = o;
}

extern "C" void kernel_launch(void* const* d_in, const int* in_sizes, int n_in,
                              void* d_out, int out_size) {
    const float* emb_users = (const float*)d_in[0];
    const float* emb_items = (const float*)d_in[1];
    const float* W1 = (const float*)d_in[2];
    const float* b1 = (const float*)d_in[3];
    const float* W2 = (const float*)d_in[4];
    const float* b2 = (const float*)d_in[5];
    const void*  ei = d_in[6];

    int NU = in_sizes[0] / D;
    int NI = in_sizes[1] / D;
    int N  = NU + NI;
    int E  = in_sizes[6] / 2;

    float* out0 = (float*)d_out;
    float* out1 = out0 + (size_t)N * D;
    float* out2 = out1 + (size_t)N * D;

    const int T = 256;
    int gN  = (N + T - 1) / T;
    int gE8 = (int)(((long long)E / 8 + T) / T);   // 8 edges/thread (ceil)
    int gW  = (int)(((long long)N * 32 + T - 1) / T);
    int gG  = (N + 127) / 128;

    k_probe<<<1, 256>>>((const unsigned long long*)ei, N);
    k_count<<<gE8, T>>>(ei, E, N);
    k_scan<<<gN, T>>>(N);
    k_gemm1_build<<<gG + gE8, T>>>((const float4*)emb_users,
                                   (const float4*)emb_items,
                                   W1, (float4*)out0, NU * 16, N, gG, ei, E);
    k_agg<<<gW, T>>>(b1, out1, N);
    k_gemm_l2<<<gG, T>>>(out1, W2, N);
    k_agg<<<gW, T>>>(b2, out2, N);
}

// round 16
// speedup vs baseline: 1.0311x; 1.0311x over previous
#include <cuda_runtime.h>
#include <cuda_fp16.h>
#include <cuda_bf16.h>
#include <cstdint>

// GNN_26242250178821: 2-layer GCN forward, CSR-gather + fp16 feature rows.
// R16: R14's proven 4-edge build / 2-edge count restored (R15's 8/thread
// regressed: atomic chains are concurrency-bound, not per-thread-MLP-bound),
// keeping R15's 1-block probe + scan-folded zeroing.
//
// RULE: never pass a __device__ symbol as a kernel argument from host code —
// on GB300/ATS the host-shadow address is silently writable.

#define D 64
#define MAXN 150016
#define MAXE  3000064
#define MAXELEM (150016 * 64)
#define MAXB 1024

__device__ int    g_deg[MAXN];     // zero at load; scan re-zeroes after use
__device__ int    g_off[MAXN + 1];
__device__ int    g_pos[MAXN];
__device__ float  g_dinv[MAXN];
__device__ int    g_bsum[MAXB];
__device__ int    g_cnt;           // zero at load; build resets after scan
__device__ int    g_src[MAXE];     // CSR payload: src index only
__device__ __half g_xwh[MAXELEM];  // rows = xw * dinv[row], fp16, 128 B/row
__device__ int    g_idx64;

// 1-block probe: dtype detect + zero sentinel row n of g_xwh.
__global__ void k_probe(const unsigned long long* __restrict__ p, int n) {
    __shared__ int any;
    if (threadIdx.x == 0) any = 0;
    __syncthreads();
    if ((p[threadIdx.x] >> 32) != 0ull) any = 1;
    if (threadIdx.x < 32)
        ((uint32_t*)g_xwh)[(size_t)n * 32 + threadIdx.x] = 0u;
    __syncthreads();
    if (threadIdx.x == 0) g_idx64 = any ? 0 : 1;
}

// Degree count: 2 edges/thread (R14-proven), fire-and-forget REDs.
__global__ void k_count(const void* __restrict__ ei, int e, int n) {
    int i = (blockIdx.x * blockDim.x + threadIdx.x) * 2;
    if (i >= e) return;
    int c0, c1 = -1;
    if (i + 1 < e) {
        if (g_idx64) {
            longlong2 v = *(const longlong2*)((const long long*)ei + (size_t)e + i);
            c0 = (int)v.x; c1 = (int)v.y;
        } else {
            int2 v = *(const int2*)((const int*)ei + (size_t)e + i);
            c0 = v.x; c1 = v.y;
        }
    } else {
        c0 = g_idx64 ? (int)((const long long*)ei)[(size_t)e + i]
                     : ((const int*)ei)[(size_t)e + i];
    }
    if ((unsigned)c0 < (unsigned)n) atomicAdd(&g_deg[c0], 1);
    if (c1 >= 0 && (unsigned)c1 < (unsigned)n) atomicAdd(&g_deg[c1], 1);
}

// Single-kernel scan, grid-resident spin sync; re-zeroes g_deg after read.
__global__ void __launch_bounds__(256, 8) k_scan(int n) {
    __shared__ int wsum[8];
    __shared__ int s_bpre;
    int tid = threadIdx.x, lane = tid & 31, wid = tid >> 5;
    int i = blockIdx.x * 256 + tid;
    int d = (i < n) ? g_deg[i] : 0;
    if (i < n) g_deg[i] = 0;              // restore invariant for next call
    int v = d;
    #pragma unroll
    for (int o = 1; o < 32; o <<= 1) {
        int t = __shfl_up_sync(~0u, v, o);
        if (lane >= o) v += t;
    }
    if (lane == 31) wsum[wid] = v;
    __syncthreads();
    if (wid == 0 && lane < 8) {
        int w = wsum[lane];
        #pragma unroll
        for (int o = 1; o < 8; o <<= 1) {
            int t = __shfl_up_sync(0xFFu, w, o);
            if (lane >= o) w += t;
        }
        wsum[lane] = w;
    }
    __syncthreads();
    int excl_blk = v - d + (wid > 0 ? wsum[wid - 1] : 0);
    int blk_total = wsum[7];

    if (tid == 0) {
        ((volatile int*)g_bsum)[blockIdx.x] = blk_total;
        __threadfence();
        atomicAdd(&g_cnt, 1);
    }
    volatile int* cnt = &g_cnt;
    while (*cnt < (int)gridDim.x) { }
    __syncthreads();

    {
        int part = 0;
        for (int bkt = tid; bkt < (int)blockIdx.x; bkt += 256)
            part += ((volatile int*)g_bsum)[bkt];
        #pragma unroll
        for (int o = 16; o > 0; o >>= 1) part += __shfl_down_sync(~0u, part, o);
        if (lane == 0) wsum[wid] = part;
        __syncthreads();
        if (tid == 0) {
            int s = 0;
            #pragma unroll
            for (int w = 0; w < 8; w++) s += wsum[w];
            s_bpre = s;
        }
        __syncthreads();
    }

    int excl = excl_blk + s_bpre;
    if (i < n) {
        g_off[i] = excl;
        g_pos[i] = excl;
        g_dinv[i] = rsqrtf((float)d + 1.0f);
        if (i == n - 1) g_off[n] = excl + d;
    }
}

// ---------------- tensor-core GEMM core (rows scaled by dinv) --------------

__device__ __forceinline__ void ldsm_x4(uint32_t& r0, uint32_t& r1,
                                        uint32_t& r2, uint32_t& r3, uint32_t a) {
    asm volatile("ldmatrix.sync.aligned.m8n8.x4.shared.b16 {%0,%1,%2,%3},[%4];"
                 : "=r"(r0), "=r"(r1), "=r"(r2), "=r"(r3) : "r"(a));
}
__device__ __forceinline__ void ldsm_x4t(uint32_t& r0, uint32_t& r1,
                                         uint32_t& r2, uint32_t& r3, uint32_t a) {
    asm volatile("ldmatrix.sync.aligned.m8n8.x4.trans.shared.b16 {%0,%1,%2,%3},[%4];"
                 : "=r"(r0), "=r"(r1), "=r"(r2), "=r"(r3) : "r"(a));
}
__device__ __forceinline__ void mma16816(float* d, uint32_t a0, uint32_t a1,
                                         uint32_t a2, uint32_t a3,
                                         uint32_t b0, uint32_t b1) {
    asm volatile(
        "mma.sync.aligned.m16n8k16.row.col.f32.f16.f16.f32 "
        "{%0,%1,%2,%3},{%4,%5,%6,%7},{%8,%9},{%0,%1,%2,%3};"
        : "+f"(d[0]), "+f"(d[1]), "+f"(d[2]), "+f"(d[3])
        : "r"(a0), "r"(a1), "r"(a2), "r"(a3), "r"(b0), "r"(b1));
}

__device__ __forceinline__ void gemm_core(const __half* xs, const __half* Ws,
                                          int row0, int n) {
    int tid = threadIdx.x;
    int warp = tid >> 5, lane = tid & 31;
    int warpRow = warp * 16;

    float d[8][4];
    #pragma unroll
    for (int t = 0; t < 8; t++)
        #pragma unroll
        for (int q = 0; q < 4; q++) d[t][q] = 0.0f;

    int rin = lane & 15, half_sel = lane >> 4;
    #pragma unroll
    for (int ks = 0; ks < 4; ks++) {
        uint32_t a0, a1, a2, a3;
        uint32_t aaddr = (uint32_t)__cvta_generic_to_shared(
            &xs[(warpRow + rin) * 72 + ks * 16 + half_sel * 8]);
        ldsm_x4(a0, a1, a2, a3, aaddr);
        #pragma unroll
        for (int jp = 0; jp < 4; jp++) {
            uint32_t b0, b1, b2, b3;
            uint32_t baddr = (uint32_t)__cvta_generic_to_shared(
                &Ws[(ks * 16 + rin) * 72 + (jp * 2 + half_sel) * 8]);
            ldsm_x4t(b0, b1, b2, b3, baddr);
            mma16816(d[jp * 2],     a0, a1, a2, a3, b0, b1);
            mma16816(d[jp * 2 + 1], a0, a1, a2, a3, b2, b3);
        }
    }

    int group = lane >> 2, tig = lane & 3;
    int row_lo = row0 + warpRow + group;
    int row_hi = row_lo + 8;
    float dv_lo = (row_lo < n) ? g_dinv[row_lo] : 0.0f;
    float dv_hi = (row_hi < n) ? g_dinv[row_hi] : 0.0f;
    __half2* xwh2 = (__half2*)g_xwh;
    #pragma unroll
    for (int t = 0; t < 8; t++) {
        int cidx = t * 4 + tig;
        if (row_lo < n)
            xwh2[(size_t)row_lo * 32 + cidx] =
                __floats2half2_rn(d[t][0] * dv_lo, d[t][1] * dv_lo);
        if (row_hi < n)
            xwh2[(size_t)row_hi * 32 + cidx] =
                __floats2half2_rn(d[t][2] * dv_hi, d[t][3] * dv_hi);
    }
}

__device__ __forceinline__ void stage_W(const float* __restrict__ W, __half* Ws) {
    const float2* W2 = (const float2*)W;
    for (int i = threadIdx.x; i < 2048; i += 256) {
        int k = i >> 5, np = i & 31;
        float2 w = W2[i];
        *(__half2*)&Ws[k * 72 + np * 2] = __floats2half2_rn(w.x, w.y);
    }
}

// Layer-1 GEMM (fused concat-out0, dinv-scaled) grid-fused with CSR build.
// blocks [0, gemmBlocks): GEMM; blocks >= gemmBlocks: build (4 edges/thread).
__global__ void __launch_bounds__(256) k_gemm1_build(
        const float4* __restrict__ u, const float4* __restrict__ it,
        const float* __restrict__ W, float4* __restrict__ out0,
        int nu4, int n, int gemmBlocks, const void* __restrict__ ei, int e) {
    __shared__ __half xs[128 * 72];
    __shared__ __half Ws[64 * 72];

    if (blockIdx.x >= (unsigned)gemmBlocks) {
        if (blockIdx.x == (unsigned)gemmBlocks && threadIdx.x == 0)
            g_cnt = 0;   // reset scan spin counter for next call
        int bid = blockIdx.x - gemmBlocks;
        long long i = ((long long)bid * 256 + threadIdx.x) * 4;
        if (i >= e) return;
        int r[4], c[4], m = (e - i >= 4) ? 4 : (int)(e - i);
        if (m == 4) {
            if (g_idx64) {
                longlong2 ra = *(const longlong2*)((const long long*)ei + i);
                longlong2 rb = *(const longlong2*)((const long long*)ei + i + 2);
                longlong2 ca = *(const longlong2*)((const long long*)ei + (size_t)e + i);
                longlong2 cb = *(const longlong2*)((const long long*)ei + (size_t)e + i + 2);
                r[0] = (int)ra.x; r[1] = (int)ra.y; r[2] = (int)rb.x; r[3] = (int)rb.y;
                c[0] = (int)ca.x; c[1] = (int)ca.y; c[2] = (int)cb.x; c[3] = (int)cb.y;
            } else {
                int4 rv = *(const int4*)((const int*)ei + i);
                int4 cv = *(const int4*)((const int*)ei + (size_t)e + i);
                r[0] = rv.x; r[1] = rv.y; r[2] = rv.z; r[3] = rv.w;
                c[0] = cv.x; c[1] = cv.y; c[2] = cv.z; c[3] = cv.w;
            }
        } else {
            for (int t = 0; t < m; t++) {
                if (g_idx64) {
                    r[t] = (int)((const long long*)ei)[i + t];
                    c[t] = (int)((const long long*)ei)[(size_t)e + i + t];
                } else {
                    r[t] = ((const int*)ei)[i + t];
                    c[t] = ((const int*)ei)[(size_t)e + i + t];
                }
            }
            for (int t = m; t < 4; t++) { r[t] = -1; c[t] = -1; }
        }
        #pragma unroll
        for (int t = 0; t < 4; t++) {
            if ((unsigned)r[t] < (unsigned)n && (unsigned)c[t] < (unsigned)n) {
                int p = atomicAdd(&g_pos[c[t]], 1);
                g_src[p] = r[t];
            }
        }
        return;
    }

    int tid = threadIdx.x;
    int row0 = blockIdx.x * 128;
    int nr = n - row0; if (nr > 128) nr = 128;

    stage_W(W, Ws);
    {
        int tot4 = nr * 16, g0 = row0 * 16;
        for (int i = tid; i < tot4; i += 256) {
            int gi = g0 + i;
            float4 v = (gi < nu4) ? u[gi] : it[gi - nu4];
            out0[gi] = v;
            int row = i >> 4, k4 = i & 15;
            __half2* p = (__half2*)&xs[row * 72 + k4 * 4];
            p[0] = __floats2half2_rn(v.x, v.y);
            p[1] = __floats2half2_rn(v.z, v.w);
        }
        for (int i = nr * 16 + tid; i < 128 * 16; i += 256) {
            int row = i >> 4, k4 = i & 15;
            __half2* p = (__half2*)&xs[row * 72 + k4 * 4];
            p[0] = __half2half2(__float2half(0.0f));
            p[1] = __half2half2(__float2half(0.0f));
        }
    }
    __syncthreads();
    gemm_core(xs, Ws, row0, n);
}

// Layer-2 GEMM: reads out1 fp32 with relu, stores dinv-scaled rows.
__global__ void __launch_bounds__(256) k_gemm_l2(
        const float* __restrict__ x, const float* __restrict__ W, int n) {
    __shared__ __half xs[128 * 72];
    __shared__ __half Ws[64 * 72];
    int tid = threadIdx.x;
    int row0 = blockIdx.x * 128;
    int nr = n - row0; if (nr > 128) nr = 128;

    stage_W(W, Ws);
    {
        const float4* x4 = (const float4*)(x + (size_t)row0 * 64);
        int tot4 = nr * 16;
        for (int i = tid; i < tot4; i += 256) {
            float4 v = x4[i];
            v.x = fmaxf(v.x, 0.0f); v.y = fmaxf(v.y, 0.0f);
            v.z = fmaxf(v.z, 0.0f); v.w = fmaxf(v.w, 0.0f);
            int row = i >> 4, k4 = i & 15;
            __half2* p = (__half2*)&xs[row * 72 + k4 * 4];
            p[0] = __floats2half2_rn(v.x, v.y);
            p[1] = __floats2half2_rn(v.z, v.w);
        }
        for (int i = nr * 16 + tid; i < 128 * 16; i += 256) {
            int row = i >> 4, k4 = i & 15;
            __half2* p = (__half2*)&xs[row * 72 + k4 * 4];
            p[0] = __half2half2(__float2half(0.0f));
            p[1] = __half2half2(__float2half(0.0f));
        }
    }
    __syncthreads();
    gemm_core(xs, Ws, row0, n);
}

// Warp per node; lane owns dims {2*lane, 2*lane+1}. Rows pre-scaled by
// dinv[src]; OOB lanes use sentinel zero row n.
// out[i] = dinv[i] * (sum + xws[i]) + b
__global__ void k_agg(const float* __restrict__ b, float* __restrict__ out, int n) {
    int node = (blockIdx.x * blockDim.x + threadIdx.x) >> 5;
    int lane = threadIdx.x & 31;
    if (node >= n) return;

    int p0 = g_off[node];
    int p1 = g_off[node + 1];
    float acc0 = 0.0f, acc1 = 0.0f;

    const __half2* xw2 = (const __half2*)g_xwh;

    int p = p0;
    while (p < p1) {
        int cnt = p1 - p; if (cnt > 32) cnt = 32;
        int meta = n;                       // sentinel zero row
        if (p + lane < p1) meta = __ldg(&g_src[p + lane]);

        int nb = (cnt + 7) >> 3;
        for (int jb = 0; jb < nb; jb++) {
            __half2 h[8];
            #pragma unroll
            for (int t = 0; t < 8; t++) {
                unsigned r = (unsigned)__shfl_sync(~0u, meta, jb * 8 + t);
                h[t] = __ldg(&xw2[r * 32u + (unsigned)lane]);
            }
            #pragma unroll
            for (int t = 0; t < 8; t++) {
                float2 f = __half22float2(h[t]);
                acc0 += f.x;
                acc1 += f.y;
            }
        }
        p += cnt;
    }

    float di = g_dinv[node];
    float2 fs = __half22float2(xw2[(unsigned)node * 32u + (unsigned)lane]);
    float2 bb = ((const float2*)b)[lane];
    float2 o;
    o.x = fmaf(di, acc0 + fs.x, bb.x);
    o.y = fmaf(di, acc1 + fs.y, bb.y);
    ((float2*)out)[(unsigned)node * 32u + (unsigned)lane] = o;
}

extern "C" void kernel_launch(void* const* d_in, const int* in_sizes, int n_in,
                              void* d_out, int out_size) {
    const float* emb_users = (const float*)d_in[0];
    const float* emb_items = (const float*)d_in[1];
    const float* W1 = (const float*)d_in[2];
    const float* b1 = (const float*)d_in[3];
    const float* W2 = (const float*)d_in[4];
    const float* b2 = (const float*)d_in[5];
    const void*  ei = d_in[6];

    int NU = in_sizes[0] / D;
    int NI = in_sizes[1] / D;
    int N  = NU + NI;
    int E  = in_sizes[6] / 2;

    float* out0 = (float*)d_out;
    float* out1 = out0 + (size_t)N * D;
    float* out2 = out1 + (size_t)N * D;

    const int T = 256;
    int gN  = (N + T - 1) / T;
    int gE2 = (E / 2 + T - 1) / T;
    int gE4 = (E / 4 + T - 1) / T;
    int gW  = (int)(((long long)N * 32 + T - 1) / T);
    int gG  = (N + 127) / 128;

    k_probe<<<1, 256>>>((const unsigned long long*)ei, N);
    k_count<<<gE2, T>>>(ei, E, N);
    k_scan<<<gN, T>>>(N);
    k_gemm1_build<<<gG + gE4, T>>>((const float4*)emb_users,
                                   (const float4*)emb_items,
                                   W1, (float4*)out0, NU * 16, N, gG, ei, E);
    k_agg<<<gW, T>>>(b1, out1, N);
    k_gemm_l2<<<gG, T>>>(out1, W2, N);
    k_agg<<<gW, T>>>(b2, out2, N);
}